// round 1
// baseline (speedup 1.0000x reference)
#include <cuda_runtime.h>
#include <cuda_bf16.h>
#include <stdint.h>

// Problem constants (match reference)
#define BATCH      32
#define SEQ_T      512
#define DIM        512
#define MAX_FRAMES 4096

// frame -> source-row map; -1 means masked (write zeros).
// 32 * 4096 * 2 B = 256 KB static device scratch (allowed).
__device__ int16_t g_frame2row[BATCH * MAX_FRAMES];

// ---------------------------------------------------------------------------
// Kernel A: per-batch inclusive scan of durations + scatter frame->row map.
// One block per batch, 512 threads (one per t).
// ---------------------------------------------------------------------------
__global__ void lr_scan_map_kernel(const int* __restrict__ durations,
                                   float* __restrict__ mel_lens_out)
{
    const int b = blockIdx.x;
    const int t = threadIdx.x;           // 0..511

    __shared__ int s_ends[SEQ_T];

    int d = durations[b * SEQ_T + t];
    s_ends[t] = d;
    __syncthreads();

    // Hillis-Steele inclusive scan over 512 elements (9 steps)
    #pragma unroll
    for (int off = 1; off < SEQ_T; off <<= 1) {
        int v = (t >= off) ? s_ends[t - off] : 0;
        __syncthreads();
        s_ends[t] += v;
        __syncthreads();
    }

    const int end   = s_ends[t];
    const int start = (t > 0) ? s_ends[t - 1] : 0;
    const int total = s_ends[SEQ_T - 1];     // <= 512*7 = 3584 < 4096

    int16_t* f2r = g_frame2row + b * MAX_FRAMES;

    // Scatter this row's index into its frame span (duration <= 7 writes)
    for (int p = start; p < end; ++p)
        f2r[p] = (int16_t)t;

    // Masked tail: frames [total, MAX_FRAMES) -> -1
    for (int p = total + t; p < MAX_FRAMES; p += SEQ_T)
        f2r[p] = (int16_t)(-1);

    // mel_lens = max(total, 1), written as float at the output tail
    if (t == 0)
        mel_lens_out[b] = (float)(total > 0 ? total : 1);
}

// ---------------------------------------------------------------------------
// Kernel B: gather/expand. One block per output row (b, frame).
// 128 threads x float4 = 512 floats per row. Coalesced both sides.
// ---------------------------------------------------------------------------
__global__ void __launch_bounds__(128)
lr_gather_kernel(const float* __restrict__ x,
                 float* __restrict__ out)
{
    const int row = blockIdx.x;                   // 0 .. BATCH*MAX_FRAMES-1
    const int b   = row >> 12;                    // /4096
    const int r   = (int)g_frame2row[row];        // broadcast load (L2-resident)

    float4* __restrict__ orow = (float4*)(out + (size_t)row * DIM);
    const int lane = threadIdx.x;                 // 0..127

    if (r < 0) {
        orow[lane] = make_float4(0.f, 0.f, 0.f, 0.f);
    } else {
        const float4* __restrict__ xrow =
            (const float4*)(x + ((size_t)b * SEQ_T + r) * DIM);
        orow[lane] = xrow[lane];
    }
}

// ---------------------------------------------------------------------------
// Launch
// ---------------------------------------------------------------------------
extern "C" void kernel_launch(void* const* d_in, const int* in_sizes, int n_in,
                              void* d_out, int out_size)
{
    const float* x         = (const float*)d_in[0];   // (32, 512, 512) f32
    const int*   durations = (const int*)d_in[1];     // (32, 512) i32
    float* out = (float*)d_out;

    // mel_lens lives after the (32,4096,512) tensor in the flattened output
    float* mel_lens_out = out + (size_t)BATCH * MAX_FRAMES * DIM;

    lr_scan_map_kernel<<<BATCH, SEQ_T>>>(durations, mel_lens_out);
    lr_gather_kernel<<<BATCH * MAX_FRAMES, 128>>>(x, out);
}

// round 2
// speedup vs baseline: 1.5826x; 1.5826x over previous
#include <cuda_runtime.h>
#include <cuda_bf16.h>
#include <stdint.h>

#define BATCH      32
#define SEQ_T      512
#define DIM        512
#define MAX_FRAMES 4096
#define F4_PER_ROW (DIM / 4)                         // 128
#define N_F4       (BATCH * MAX_FRAMES * F4_PER_ROW) // 16,777,216

// frame -> source-row map; -1 means masked. 256 KB static scratch.
__device__ int16_t g_frame2row[BATCH * MAX_FRAMES];

// ---------------------------------------------------------------------------
// Kernel A: per-batch inclusive scan (warp-shuffle) + scatter frame->row map.
// One block per batch, 512 threads.
// ---------------------------------------------------------------------------
__global__ void lr_scan_map_kernel(const int* __restrict__ durations,
                                   float* __restrict__ mel_lens_out)
{
    const int b    = blockIdx.x;
    const int t    = threadIdx.x;       // 0..511
    const int lane = t & 31;
    const int warp = t >> 5;            // 0..15

    __shared__ int s_warpsum[16];
    __shared__ int s_total;

    int d = durations[b * SEQ_T + t];

    // intra-warp inclusive scan
    int v = d;
    #pragma unroll
    for (int off = 1; off < 32; off <<= 1) {
        int n = __shfl_up_sync(0xffffffffu, v, off);
        if (lane >= off) v += n;
    }
    if (lane == 31) s_warpsum[warp] = v;
    __syncthreads();

    // warp 0 scans the 16 warp sums
    if (warp == 0) {
        int ws = (lane < 16) ? s_warpsum[lane] : 0;
        #pragma unroll
        for (int off = 1; off < 16; off <<= 1) {
            int n = __shfl_up_sync(0xffffffffu, ws, off);
            if (lane >= off) ws += n;
        }
        if (lane < 16) s_warpsum[lane] = ws;
        if (lane == 15) s_total = ws;
    }
    __syncthreads();

    const int warp_off = (warp > 0) ? s_warpsum[warp - 1] : 0;
    const int end      = warp_off + v;
    const int start    = end - d;
    const int total    = s_total;        // <= 512*7 = 3584 < 4096

    int16_t* f2r = g_frame2row + b * MAX_FRAMES;

    for (int p = start; p < end; ++p)
        f2r[p] = (int16_t)t;

    for (int p = total + t; p < MAX_FRAMES; p += SEQ_T)
        f2r[p] = (int16_t)(-1);

    if (t == 0)
        mel_lens_out[b] = (float)(total > 0 ? total : 1);
}

// ---------------------------------------------------------------------------
// Kernel B: gather/expand over flat float4 index space.
// K=8 independent chains per thread for high MLP; streaming stores.
// ---------------------------------------------------------------------------
#define GATHER_BLOCK 256
#define GATHER_K     8
#define GATHER_GRID  (N_F4 / (GATHER_BLOCK * GATHER_K))   // 8192

__global__ void __launch_bounds__(GATHER_BLOCK)
lr_gather_kernel(const float4* __restrict__ x,
                 float4* __restrict__ out)
{
    const int tid    = blockIdx.x * GATHER_BLOCK + threadIdx.x;
    const int stride = GATHER_GRID * GATHER_BLOCK;        // N_F4 / 8

    int   idx[GATHER_K];
    int   r  [GATHER_K];

    // phase 1: batched f2r loads (uniform per warp -> broadcast hits)
    #pragma unroll
    for (int k = 0; k < GATHER_K; ++k) {
        idx[k] = tid + k * stride;
        const int row = idx[k] >> 7;                      // / F4_PER_ROW
        r[k] = (int)g_frame2row[row];
    }

    // phase 2: batched x loads (8 independent DRAM/L2 chains in flight)
    float4 vv[GATHER_K];
    #pragma unroll
    for (int k = 0; k < GATHER_K; ++k) {
        if (r[k] < 0) {
            vv[k] = make_float4(0.f, 0.f, 0.f, 0.f);
        } else {
            const int b    = idx[k] >> 19;                // / (4096*128)
            const int lane = idx[k] & (F4_PER_ROW - 1);
            vv[k] = __ldg(&x[((size_t)b * SEQ_T + r[k]) * F4_PER_ROW + lane]);
        }
    }

    // phase 3: streaming stores (evict-first; output never re-read)
    #pragma unroll
    for (int k = 0; k < GATHER_K; ++k)
        __stcs(&out[idx[k]], vv[k]);
}

// ---------------------------------------------------------------------------
extern "C" void kernel_launch(void* const* d_in, const int* in_sizes, int n_in,
                              void* d_out, int out_size)
{
    const float* x         = (const float*)d_in[0];   // (32, 512, 512) f32
    const int*   durations = (const int*)d_in[1];     // (32, 512) i32
    float* out = (float*)d_out;

    float* mel_lens_out = out + (size_t)BATCH * MAX_FRAMES * DIM;

    lr_scan_map_kernel<<<BATCH, SEQ_T>>>(durations, mel_lens_out);
    lr_gather_kernel<<<GATHER_GRID, GATHER_BLOCK>>>((const float4*)x,
                                                    (float4*)out);
}